// round 16
// baseline (speedup 1.0000x reference)
#include <cuda_runtime.h>
#include <cuda_fp16.h>
#include <math.h>
#include <stdint.h>

#define N_NODES 100000
#define NFEAT   256
#define HID     32
#define NCOL    64
#define TILE_M  128
#define NT      782          // ceil(100000/128)
#define GRID    444          // 148 SMs x 3 CTAs -> exactly one wave

// B smem: 64 rows x 264 fp16 (528B padded rows, conflict-free ldmatrix phases)
#define BROW_B   528
#define B_BYTES  (NCOL * BROW_B)     // 33792
#define B_HI_OFF 0
#define BIAS_OFF B_BYTES                   // 64 f32
#define WLIN_OFF (BIAS_OFF + 256)          // 32 f32
#define BLIN_OFF (WLIN_OFF + 128)
#define SMEM_TOTAL (BLIN_OFF + 16)         // ~34.2 KB

// persistent device scratch (prep output; W stored K-PERMUTED within 16-blocks)
__device__ __half g_W16[NCOL * NFEAT];
__device__ float g_bias[NCOL];
__device__ float g_wlin[HID];
__device__ float g_blin;

// logical fragment position p -> physical k within a 16-block, so that lane t's
// float4 at physical cols 4t..4t+3 lands at logical (2t,2t+1,2t+8,2t+9)
__device__ __forceinline__ int kperm(int p) {
    return (p < 8) ? (4 * (p >> 1) + (p & 1))
                   : (4 * ((p - 8) >> 1) + 2 + (p & 1));
}

__global__ void prep_kernel(const float* __restrict__ Wz, const float* __restrict__ bz,
                            const float* __restrict__ Wh, const float* __restrict__ bh,
                            const float* __restrict__ Wlin, const float* __restrict__ blin)
{
    int idx = blockIdx.x * blockDim.x + threadIdx.x;
    if (idx < NCOL * NFEAT) {
        int n = idx / NFEAT, k = idx % NFEAT;               // k = logical position
        int kp = (k & ~15) | kperm(k & 15);                 // physical source col
        const float* W = (n < HID) ? Wz : Wh;               // (2,1,288,32) row-major
        int nn = n & (HID - 1);
        float w = W[kp * HID + nn] + W[288 * HID + kp * HID + nn];
        g_W16[idx] = __float2half_rn(w);
    }
    if (blockIdx.x == 0) {
        int t = threadIdx.x;
        if (t < NCOL) g_bias[t] = (t < HID) ? bz[t] : bh[t - HID];
        if (t < HID)  g_wlin[t] = Wlin[t];
        if (t == 0)   g_blin = blin[0];
    }
}

// ---------- helpers ----------
#define MMA(acc, a, b0, b1) \
    asm("mma.sync.aligned.m16n8k16.row.col.f32.f16.f16.f32 " \
        "{%0,%1,%2,%3}, {%4,%5,%6,%7}, {%8,%9}, {%0,%1,%2,%3};" \
        : "+f"((acc)[0]), "+f"((acc)[1]), "+f"((acc)[2]), "+f"((acc)[3]) \
        : "r"((a)[0]), "r"((a)[1]), "r"((a)[2]), "r"((a)[3]), "r"(b0), "r"(b1))

#define LDM4(r, addr) \
    asm("ldmatrix.sync.aligned.m8n8.x4.shared.b16 {%0,%1,%2,%3}, [%4];" \
        : "=r"((r)[0]), "=r"((r)[1]), "=r"((r)[2]), "=r"((r)[3]) : "r"(addr))

// pack (fx,fy) -> fp16x2
#define CVT2(h, fx, fy) \
    asm("cvt.rn.f16x2.f32 %0, %1, %2;" : "=r"(h) : "f"(fy), "f"(fx))

// streaming 128b load (evict-first: x is read exactly once)
#define LDG_CS(v, p) \
    asm("ld.global.cs.v4.f32 {%0,%1,%2,%3}, [%4];" \
        : "=f"((v).x), "=f"((v).y), "=f"((v).z), "=f"((v).w) : "l"(p))

#define PREFETCH_L2(p) asm volatile("prefetch.global.L2 [%0];" :: "l"(p))

#define STG_CS(p, v) asm volatile("st.global.cs.f32 [%0], %1;" :: "l"(p), "f"(v))

__device__ __forceinline__ float fast_tanh(float v) {
    return 1.0f - 2.0f / (__expf(2.0f * v) + 1.0f);
}

extern __shared__ __align__(128) char smem[];

__global__ __launch_bounds__(256, 3)
void gcn_hmma_kernel(const float* __restrict__ x, float* __restrict__ out)
{
    const int tid  = threadIdx.x;
    const uint32_t sbase = (uint32_t)__cvta_generic_to_shared(smem);

    const int warp = tid >> 5, lane = tid & 31;
    const int g = lane >> 2, t = lane & 3;

    // ---- stage fp16 W once; reused for both tiles ----
    {
        const uint2* w16 = reinterpret_cast<const uint2*>(g_W16);
#pragma unroll
        for (int i = 0; i < 16; i++) {
            int idx = tid + i * 256;          // 0..4095
            int n = idx >> 6, c = idx & 63;   // 64 chunks of 4 fp16 per row
            *reinterpret_cast<uint2*>(smem + B_HI_OFF + n * BROW_B + c * 8) = w16[idx];
        }
    }
    if (tid < NCOL) reinterpret_cast<float*>(smem + BIAS_OFF)[tid] = g_bias[tid];
    if (tid < HID)  reinterpret_cast<float*>(smem + WLIN_OFF)[tid] = g_wlin[tid];
    if (tid == 0)   reinterpret_cast<float*>(smem + BLIN_OFF)[0] = g_blin;
    __syncthreads();

    // ldmatrix per-lane address (logical layout; matches permuted-stored W)
    const int lm_n = ((lane >> 4) & 1) * 8 + (lane & 7);
    const int lm_k = ((lane >> 3) & 1) * 8;
    const uint32_t lmhi = sbase + B_HI_OFF + lm_n * BROW_B + lm_k * 2;

    const float* sBias = reinterpret_cast<const float*>(smem + BIAS_OFF);
    const float* sWlin = reinterpret_cast<const float*>(smem + WLIN_OFF);
    const float  blin  = reinterpret_cast<const float*>(smem + BLIN_OFF)[0];

    for (int tile = blockIdx.x; tile < NT; tile += GRID) {
        const int nodeBase = tile * TILE_M + warp * 16;
        const int r0 = nodeBase + g, r1 = r0 + 8;
        const int cr0 = (r0 < N_NODES) ? r0 : (N_NODES - 1);
        const int cr1 = (r1 < N_NODES) ? r1 : (N_NODES - 1);
        const float4* p0 = reinterpret_cast<const float4*>(x) + (size_t)cr0 * 64 + t;
        const float4* p1 = reinterpret_cast<const float4*>(x) + (size_t)cr1 * 64 + t;

        float4 c0, c1;
        LDG_CS(c0, p0);
        LDG_CS(c1, p1);
        PREFETCH_L2(p0 + 4);
        PREFETCH_L2(p1 + 4);

        float acc[8][4];
#pragma unroll
        for (int i = 0; i < 8; i++)
#pragma unroll
            for (int j = 0; j < 4; j++) acc[i][j] = 0.0f;

#pragma unroll 2
        for (int ks = 0; ks < 16; ks++) {
            // 1-deep register pipeline + distance-2 L2 prefetch
            float4 n0, n1;
            if (ks < 15) {
                LDG_CS(n0, p0 + (ks + 1) * 4);
                LDG_CS(n1, p1 + (ks + 1) * 4);
            }
            if (ks < 14) {
                PREFETCH_L2(p0 + (ks + 2) * 4);
                PREFETCH_L2(p1 + (ks + 2) * 4);
            }

            uint32_t a[4];
            CVT2(a[0], c0.x, c0.y);
            CVT2(a[1], c1.x, c1.y);
            CVT2(a[2], c0.z, c0.w);
            CVT2(a[3], c1.z, c1.w);

#pragma unroll
            for (int nt2 = 0; nt2 < 4; nt2++) {
                uint32_t bh[4];
                LDM4(bh, lmhi + nt2 * (16 * BROW_B) + ks * 32);
                MMA(acc[2 * nt2],     a, bh[0], bh[1]);
                MMA(acc[2 * nt2 + 1], a, bh[2], bh[3]);
            }

            c0 = n0;
            c1 = n1;
        }

        // ---- epilogue: register/shuffle based ----
#pragma unroll
        for (int row = 0; row < 2; row++) {
            float s = 0.0f;
#pragma unroll
            for (int nt = 0; nt < 4; nt++) {
#pragma unroll
                for (int j = 0; j < 2; j++) {
                    int c = nt * 8 + 2 * t + j;
                    float zv = acc[nt][row * 2 + j]     + sBias[c];
                    float hv = acc[nt + 4][row * 2 + j] + sBias[HID + c];
                    float z  = 1.0f / (1.0f + __expf(-zv));
                    float th = fast_tanh(hv);
                    float h  = fmaxf((1.0f - z) * th, 0.0f);
                    s = fmaf(h, sWlin[c], s);
                }
            }
            s += __shfl_xor_sync(0xffffffffu, s, 1);
            s += __shfl_xor_sync(0xffffffffu, s, 2);
            int node = row ? r1 : r0;
            if (t == 0 && node < N_NODES) STG_CS(out + node, s + blin);
        }
    }
}

extern "C" void kernel_launch(void* const* d_in, const int* in_sizes, int n_in,
                              void* d_out, int out_size)
{
    const float* x    = (const float*)d_in[0];
    const float* Wz   = (const float*)d_in[3];
    const float* bz   = (const float*)d_in[4];
    const float* Wh   = (const float*)d_in[7];
    const float* bh   = (const float*)d_in[8];
    const float* Wlin = (const float*)d_in[9];
    const float* blin = (const float*)d_in[10];
    float* out = (float*)d_out;

    prep_kernel<<<64, 256>>>(Wz, bz, Wh, bh, Wlin, blin);

    cudaFuncSetAttribute(gcn_hmma_kernel,
                         cudaFuncAttributeMaxDynamicSharedMemorySize, SMEM_TOTAL);
    gcn_hmma_kernel<<<GRID, 256, SMEM_TOTAL>>>(x, out);
}

// round 17
// speedup vs baseline: 1.1030x; 1.1030x over previous
#include <cuda_runtime.h>
#include <cuda_fp16.h>
#include <math.h>
#include <stdint.h>

#define N_NODES 100000
#define NFEAT   256
#define HID     32
#define NCOL    64
#define TILE_M  128
#define NT      782          // ceil(100000/128)
#define GRID    444          // 148 SMs x 3 CTAs

// ---- smem layout ----
// per-warp A rings: 8 warps x 4 stages x 1024B
#define NSTAGE   4
#define ASTAGE_B 1024
#define A_OFF    0
#define A_BYTES  (8 * NSTAGE * ASTAGE_B)   // 32768
#define BROW_B   528
#define B_BYTES  (NCOL * BROW_B)           // 33792
#define B_HI_OFF A_BYTES                   // 32768
#define BIAS_OFF (B_HI_OFF + B_BYTES)      // 66560
#define WLIN_OFF (BIAS_OFF + 256)
#define BLIN_OFF (WLIN_OFF + 128)
#define SMEM_TOTAL (BLIN_OFF + 16)         // 66960 -> 3 CTAs/SM

// persistent device scratch (prep output; W stored K-PERMUTED within 16-blocks)
__device__ __half g_W16[NCOL * NFEAT];
__device__ float g_bias[NCOL];
__device__ float g_wlin[HID];
__device__ float g_blin;

// logical fragment position p -> physical k within a 16-block, so that lane t's
// float4 at physical cols 4t..4t+3 lands at logical (2t,2t+1,2t+8,2t+9)
__device__ __forceinline__ int kperm(int p) {
    return (p < 8) ? (4 * (p >> 1) + (p & 1))
                   : (4 * ((p - 8) >> 1) + 2 + (p & 1));
}

__global__ void prep_kernel(const float* __restrict__ Wz, const float* __restrict__ bz,
                            const float* __restrict__ Wh, const float* __restrict__ bh,
                            const float* __restrict__ Wlin, const float* __restrict__ blin)
{
    int idx = blockIdx.x * blockDim.x + threadIdx.x;
    if (idx < NCOL * NFEAT) {
        int n = idx / NFEAT, k = idx % NFEAT;               // k = logical position
        int kp = (k & ~15) | kperm(k & 15);                 // physical source col
        const float* W = (n < HID) ? Wz : Wh;               // (2,1,288,32) row-major
        int nn = n & (HID - 1);
        float w = W[kp * HID + nn] + W[288 * HID + kp * HID + nn];
        g_W16[idx] = __float2half_rn(w);
    }
    if (blockIdx.x == 0) {
        int t = threadIdx.x;
        if (t < NCOL) g_bias[t] = (t < HID) ? bz[t] : bh[t - HID];
        if (t < HID)  g_wlin[t] = Wlin[t];
        if (t == 0)   g_blin = blin[0];
    }
}

// ---------- helpers ----------
#define MMA(acc, a, b0, b1) \
    asm("mma.sync.aligned.m16n8k16.row.col.f32.f16.f16.f32 " \
        "{%0,%1,%2,%3}, {%4,%5,%6,%7}, {%8,%9}, {%0,%1,%2,%3};" \
        : "+f"((acc)[0]), "+f"((acc)[1]), "+f"((acc)[2]), "+f"((acc)[3]) \
        : "r"((a)[0]), "r"((a)[1]), "r"((a)[2]), "r"((a)[3]), "r"(b0), "r"(b1))

#define LDM4(r, addr) \
    asm("ldmatrix.sync.aligned.m8n8.x4.shared.b16 {%0,%1,%2,%3}, [%4];" \
        : "=r"((r)[0]), "=r"((r)[1]), "=r"((r)[2]), "=r"((r)[3]) : "r"(addr))

// pack (fx,fy) -> fp16x2
#define CVT2(h, fx, fy) \
    asm("cvt.rn.f16x2.f32 %0, %1, %2;" : "=r"(h) : "f"(fy), "f"(fx))

// 16B L1-bypassing async copy
#define CPA16(sdst, gsrc) \
    asm volatile("cp.async.cg.shared.global [%0], [%1], 16;" :: "r"(sdst), "l"(gsrc))
#define CP_COMMIT() asm volatile("cp.async.commit_group;" ::: "memory")
#define CP_WAIT2()  asm volatile("cp.async.wait_group 2;" ::: "memory")

#define LDS128F(v, addr) \
    asm("ld.shared.v4.f32 {%0,%1,%2,%3}, [%4];" \
        : "=f"((v).x), "=f"((v).y), "=f"((v).z), "=f"((v).w) : "r"(addr))

#define STG_CS(p, v) asm volatile("st.global.cs.f32 [%0], %1;" :: "l"(p), "f"(v))

__device__ __forceinline__ float fast_tanh(float v) {
    return 1.0f - 2.0f / (__expf(2.0f * v) + 1.0f);
}

extern __shared__ __align__(128) char smem[];

__global__ __launch_bounds__(256, 3)
void gcn_hmma_kernel(const float* __restrict__ x, float* __restrict__ out)
{
    const int tid  = threadIdx.x;
    const uint32_t sbase = (uint32_t)__cvta_generic_to_shared(smem);

    const int warp = tid >> 5, lane = tid & 31;
    const int g = lane >> 2, t = lane & 3;

    // ---- stage fp16 W once (persistent CTA reuses it for all tiles) ----
    {
        const uint2* w16 = reinterpret_cast<const uint2*>(g_W16);
#pragma unroll
        for (int i = 0; i < 16; i++) {
            int idx = tid + i * 256;
            int n = idx >> 6, c = idx & 63;
            *reinterpret_cast<uint2*>(smem + B_HI_OFF + n * BROW_B + c * 8) = w16[idx];
        }
    }
    if (tid < NCOL) reinterpret_cast<float*>(smem + BIAS_OFF)[tid] = g_bias[tid];
    if (tid < HID)  reinterpret_cast<float*>(smem + WLIN_OFF)[tid] = g_wlin[tid];
    if (tid == 0)   reinterpret_cast<float*>(smem + BLIN_OFF)[0] = g_blin;
    __syncthreads();

    // ldmatrix per-lane address (logical layout; matches permuted-stored W)
    const int lm_n = ((lane >> 4) & 1) * 8 + (lane & 7);
    const int lm_k = ((lane >> 3) & 1) * 8;
    const uint32_t lmhi = sbase + B_HI_OFF + lm_n * BROW_B + lm_k * 2;

    const float* sBias = reinterpret_cast<const float*>(smem + BIAS_OFF);
    const float* sWlin = reinterpret_cast<const float*>(smem + WLIN_OFF);
    const float  blin  = reinterpret_cast<const float*>(smem + BLIN_OFF)[0];

    // per-warp private A ring; lane slot: p0-frag at +lane*16, p1-frag at +512+lane*16
    const uint32_t ring = sbase + A_OFF + warp * (NSTAGE * ASTAGE_B) + lane * 16;

    for (int tile = blockIdx.x; tile < NT; tile += GRID) {
        const int nodeBase = tile * TILE_M + warp * 16;
        const int r0 = nodeBase + g, r1 = r0 + 8;
        const int cr0 = (r0 < N_NODES) ? r0 : (N_NODES - 1);
        const int cr1 = (r1 < N_NODES) ? r1 : (N_NODES - 1);
        const float4* p0 = reinterpret_cast<const float4*>(x) + (size_t)cr0 * 64 + t;
        const float4* p1 = reinterpret_cast<const float4*>(x) + (size_t)cr1 * 64 + t;

        // prologue: stages 0..2 in flight
#pragma unroll
        for (int s = 0; s < 3; s++) {
            CPA16(ring + s * ASTAGE_B,       p0 + s * 4);
            CPA16(ring + s * ASTAGE_B + 512, p1 + s * 4);
            CP_COMMIT();
        }

        float acc[8][4];
#pragma unroll
        for (int i = 0; i < 8; i++)
#pragma unroll
            for (int j = 0; j < 4; j++) acc[i][j] = 0.0f;

#pragma unroll 4
        for (int ks = 0; ks < 16; ks++) {
            CP_WAIT2();                       // stage ks complete (warp-scoped)

            if (ks < 13) {
                uint32_t sd = ring + ((ks + 3) & 3) * ASTAGE_B;
                CPA16(sd,       p0 + (ks + 3) * 4);
                CPA16(sd + 512, p1 + (ks + 3) * 4);
            }
            CP_COMMIT();                      // commit every iter (group count)

            float4 c0, c1;
            uint32_t ab = ring + (ks & 3) * ASTAGE_B;
            LDS128F(c0, ab);
            LDS128F(c1, ab + 512);

            uint32_t a[4];
            CVT2(a[0], c0.x, c0.y);
            CVT2(a[1], c1.x, c1.y);
            CVT2(a[2], c0.z, c0.w);
            CVT2(a[3], c1.z, c1.w);

#pragma unroll
            for (int nt2 = 0; nt2 < 4; nt2++) {
                uint32_t bh[4];
                LDM4(bh, lmhi + nt2 * (16 * BROW_B) + ks * 32);
                MMA(acc[2 * nt2],     a, bh[0], bh[1]);
                MMA(acc[2 * nt2 + 1], a, bh[2], bh[3]);
            }
        }

        // ---- epilogue: register/shuffle based ----
#pragma unroll
        for (int row = 0; row < 2; row++) {
            float s = 0.0f;
#pragma unroll
            for (int nt = 0; nt < 4; nt++) {
#pragma unroll
                for (int j = 0; j < 2; j++) {
                    int c = nt * 8 + 2 * t + j;
                    float zv = acc[nt][row * 2 + j]     + sBias[c];
                    float hv = acc[nt + 4][row * 2 + j] + sBias[HID + c];
                    float z  = 1.0f / (1.0f + __expf(-zv));
                    float th = fast_tanh(hv);
                    float h  = fmaxf((1.0f - z) * th, 0.0f);
                    s = fmaf(h, sWlin[c], s);
                }
            }
            s += __shfl_xor_sync(0xffffffffu, s, 1);
            s += __shfl_xor_sync(0xffffffffu, s, 2);
            int node = row ? r1 : r0;
            if (t == 0 && node < N_NODES) STG_CS(out + node, s + blin);
        }
    }
}

extern "C" void kernel_launch(void* const* d_in, const int* in_sizes, int n_in,
                              void* d_out, int out_size)
{
    const float* x    = (const float*)d_in[0];
    const float* Wz   = (const float*)d_in[3];
    const float* bz   = (const float*)d_in[4];
    const float* Wh   = (const float*)d_in[7];
    const float* bh   = (const float*)d_in[8];
    const float* Wlin = (const float*)d_in[9];
    const float* blin = (const float*)d_in[10];
    float* out = (float*)d_out;

    prep_kernel<<<64, 256>>>(Wz, bz, Wh, bh, Wlin, blin);

    cudaFuncSetAttribute(gcn_hmma_kernel,
                         cudaFuncAttributeMaxDynamicSharedMemorySize, SMEM_TOTAL);
    gcn_hmma_kernel<<<GRID, 256, SMEM_TOTAL>>>(x, out);
}